// round 12
// baseline (speedup 1.0000x reference)
#include <cuda_runtime.h>
#include <stdint.h>

// Problem constants
#define BB 4
#define CC 8192
#define HH 32
#define WW 32
#define HW 1024                 // H*W
#define CHW (CC * HW)           // 8388608
#define NPIX 4096               // B*H*W
#define ROWS 128                // B*H
#define NCHUNK 16
#define CHUNK (CC / NCHUNK)     // 512
#define DD 256                  // embedding dim
#define DS2 32                  // d per kB block
#define OH_ELEMS ((size_t)BB * CC * HW)  // 33554432

#define NRED 2048               // reduce-role blocks (16 chunks x 128 rows)
#define NZERO 2048              // zero-role blocks

// Packed per-(pixel,chunk) partials: {mxg, idx_as_float_bits, s, sx}
// Layout [NPIX][NCHUNK]: per-pixel chunks contiguous -> coalesced combine.
__device__ float4 g_pack[NPIX][NCHUNK];
// Per-row readiness: kA adds +1 per chunk (16 total); kB blocks add +256 each
// after consuming; the 8th consumer resets to 0 (deterministic graph replay).
__device__ int g_rowcnt[ROWS];

// ---------------------------------------------------------------------------
// Fused kernel A: even blocks do per-pixel partial reductions over a channel
// chunk (and publish per-row readiness); odd blocks zero-fill the one_hot
// region (untouched hot path). All blocks trigger programmatic launch
// completion at entry so kB can dispatch into freed slots during kA's tail.
// Softmax unstabilized (inputs standard-normal bounded): s = sum(exp(x)).
// ---------------------------------------------------------------------------
__global__ __launch_bounds__(256) void kA(const float* __restrict__ x,
                                          const float* __restrict__ g,
                                          float* __restrict__ out,
                                          size_t kl_off, size_t oh_off) {
    cudaTriggerProgrammaticLaunchCompletion();
    const int bid = blockIdx.x;

    if (bid & 1) {
        // ---------------- zero role ----------------
        const size_t zid = (size_t)(bid >> 1);
        if (zid == 0 && threadIdx.x == 0) out[kl_off] = 0.0f;

        float* oh = out + oh_off;
        uintptr_t addr = (uintptr_t)oh;
        int head = (int)(((16u - (unsigned)(addr & 15u)) & 15u) >> 2);
        size_t t = zid * blockDim.x + threadIdx.x;
        size_t nth = (size_t)NZERO * blockDim.x;

        if (t < (size_t)head) oh[t] = 0.0f;

        size_t n4 = (OH_ELEMS - head) >> 2;
        float4* o4 = (float4*)(oh + head);
        float4 z = make_float4(0.f, 0.f, 0.f, 0.f);
        for (size_t i = t; i < n4; i += nth) __stcs(&o4[i], z);

        size_t tail0 = (size_t)head + (n4 << 2);
        size_t ntail = OH_ELEMS - tail0;
        if (t < ntail) oh[tail0 + t] = 0.0f;
        return;
    }

    // ---------------- reduce role ----------------
    const int rid = bid >> 1;          // 0..2047
    const int chunk = rid & 15;        // 0..15
    const int row   = rid >> 4;        // 0..127 == b*32 + h
    const int b = row >> 5, h = row & 31;
    const int tid  = threadIdx.x;
    const int warp = tid >> 5, lane = tid & 31;
    const int csub = lane >> 3, wg = lane & 7;

    const size_t rowbase = (size_t)b * CHW + (size_t)h * WW + (size_t)wg * 4;
    const int c0 = chunk * CHUNK + warp * 4 + csub;

    float mxg[4], s[4], sx[4];
    int ixg[4];
#pragma unroll
    for (int j = 0; j < 4; j++) {
        mxg[j] = -1e30f; ixg[j] = 0; s[j] = 0.f; sx[j] = 0.f;
    }

#pragma unroll 4
    for (int k = 0; k < CHUNK / 32; k++) {
        const int c = c0 + k * 32;
        const float4 xv = __ldcs((const float4*)(x + rowbase + (size_t)c * HW));
        const float4 gv = __ldcs((const float4*)(g + rowbase + (size_t)c * HW));
        const float xs[4] = {xv.x, xv.y, xv.z, xv.w};
        const float gs[4] = {gv.x, gv.y, gv.z, gv.w};
#pragma unroll
        for (int j = 0; j < 4; j++) {
            const float xx = xs[j];
            const float v = xx + gs[j];
            if (v > mxg[j]) { mxg[j] = v; ixg[j] = c; }   // ascending c: '>' keeps first
            sx[j] += xx;
            s[j]  += __expf(xx);
        }
    }

    // Warp butterfly over csub (lanes differing in bits 3,4)
#pragma unroll
    for (int off = 8; off < 32; off <<= 1) {
#pragma unroll
        for (int j = 0; j < 4; j++) {
            float vm = __shfl_xor_sync(0xffffffffu, mxg[j], off);
            int   vi = __shfl_xor_sync(0xffffffffu, ixg[j], off);
            if (vm > mxg[j] || (vm == mxg[j] && vi < ixg[j])) { mxg[j] = vm; ixg[j] = vi; }
            s[j]  += __shfl_xor_sync(0xffffffffu, s[j],  off);
            sx[j] += __shfl_xor_sync(0xffffffffu, sx[j], off);
        }
    }

    __shared__ float sh_mxg[8][8][4];
    __shared__ int   sh_ixg[8][8][4];
    __shared__ float sh_s  [8][8][4];
    __shared__ float sh_sx [8][8][4];

    if (csub == 0) {
#pragma unroll
        for (int j = 0; j < 4; j++) {
            sh_mxg[warp][wg][j] = mxg[j];
            sh_ixg[warp][wg][j] = ixg[j];
            sh_s  [warp][wg][j] = s[j];
            sh_sx [warp][wg][j] = sx[j];
        }
    }
    __syncthreads();

    if (tid < 32) {
        const int wg2 = tid >> 2, j = tid & 3;
        float M = -1e30f; int I = 0;
        float S = 0.f, SX = 0.f;
#pragma unroll
        for (int w = 0; w < 8; w++) {
            float vm = sh_mxg[w][wg2][j]; int vi = sh_ixg[w][wg2][j];
            if (vm > M || (vm == M && vi < I)) { M = vm; I = vi; }
            S  += sh_s [w][wg2][j];
            SX += sh_sx[w][wg2][j];
        }
        const int p = row * 32 + wg2 * 4 + j;   // b*1024 + h*32 + w
        g_pack[p][chunk] = make_float4(M, __int_as_float(I), S, SX);
        __threadfence();                // release: only ~512B of stores to drain
        __syncwarp();
        if (tid == 0) atomicAdd(&g_rowcnt[row], 1);   // publish chunk done
    }
}

// ---------------------------------------------------------------------------
// Kernel B (combine + gather, d-sliced): block = (row, dslice), 1024 blocks.
// PDL-launched; blocks become resident during kA's tail and POLL their row's
// readiness flag (fine-grained dependency) instead of waiting for all of kA.
// dslice 0 additionally grid-syncs (full kA done => zeroing done) before
// writing the one_hot ones + KL. Gather: ONE LDG.128 per thread, padded smem
// transpose, ONE STG.128 per thread.
// ---------------------------------------------------------------------------
__global__ __launch_bounds__(256) void kB(const float* __restrict__ emb,
                                          float* __restrict__ out,
                                          size_t kl_off, size_t oh_off) {
    const int row    = blockIdx.x >> 3;   // 0..127 == b*32 + h
    const int dslice = blockIdx.x & 7;    // 0..7
    const int b = row >> 5, h = row & 31;
    const int tid = threadIdx.x;

    // Wait until this row's 16 chunk partials are published (acquire).
    if (tid == 0) {
        int v;
        while (true) {
            asm volatile("ld.acquire.gpu.global.s32 %0, [%1];"
                         : "=r"(v) : "l"(&g_rowcnt[row]) : "memory");
            if ((v & 0xff) >= NCHUNK) break;
            __nanosleep(64);
        }
    }
    __syncthreads();

    __shared__ int   sidx[32];
    __shared__ float sterm[32];
    __shared__ float sm[32][DS2 + 1];     // +1 pad (stride 33): conflict-free

    // ---- parallel combine: pixel = tid>>3, chunk-group = tid&7 (2 chunks) ----
    {
        const int px = tid >> 3, cg = tid & 7;
        const int p = row * 32 + px;
        const float4 a = g_pack[p][cg * 2 + 0];
        const float4 c = g_pack[p][cg * 2 + 1];

        float M = a.x; int I = __float_as_int(a.y);
        float S = a.z, SX = a.w;
        {
            const int vi = __float_as_int(c.y);
            if (c.x > M || (c.x == M && vi < I)) { M = c.x; I = vi; }
            S += c.z; SX += c.w;
        }
        // reduce across the 8 lanes of this pixel (xor of bits 0..2)
#pragma unroll
        for (int off = 1; off < 8; off <<= 1) {
            float vm = __shfl_xor_sync(0xffffffffu, M, off);
            int   vi = __shfl_xor_sync(0xffffffffu, I, off);
            if (vm > M || (vm == M && vi < I)) { M = vm; I = vi; }
            S  += __shfl_xor_sync(0xffffffffu, S,  off);
            SX += __shfl_xor_sync(0xffffffffu, SX, off);
        }
        if (cg == 0) {
            sidx[px] = I;
            // KL per pixel: log(1/n) - mean(x) + lse(x)
            const float LOGT = -9.010913347279288f;   // -log(8192)
            sterm[px] = LOGT - SX * (1.0f / 8192.0f) + logf(S);
        }
    }
    __syncthreads();

    // ---- gather: one LDG.128 per thread; r = tid>>3 (pixel), c4 = tid&7 ----
    {
        const int r = tid >> 3, c4 = tid & 7;
        const float4 v = __ldg((const float4*)(emb + (size_t)sidx[r] * DD
                                               + dslice * DS2 + c4 * 4));
        sm[r][c4 * 4 + 0] = v.x;
        sm[r][c4 * 4 + 1] = v.y;
        sm[r][c4 * 4 + 2] = v.z;
        sm[r][c4 * 4 + 3] = v.w;
    }
    __syncthreads();

    // ---- store quantized (disjoint from one_hot): one STG.128 per thread ----
    {
        const int d = tid >> 3, w4 = tid & 7;
        float4 v;
        v.x = sm[w4 * 4 + 0][d];
        v.y = sm[w4 * 4 + 1][d];
        v.z = sm[w4 * 4 + 2][d];
        v.w = sm[w4 * 4 + 3][d];
        float4* dst = (float4*)(out + (size_t)b * (DD * HW)
                                    + (size_t)(dslice * DS2 + d) * HW
                                    + (size_t)h * WW + w4 * 4);
        *dst = v;
    }

    // ---- dslice 0: one_hot ones + KL (requires ALL of kA: zeroing done) ----
    if (dslice == 0) {
        cudaGridDependencySynchronize();
        if (tid < 32) {
            out[oh_off + (size_t)b * CHW + (size_t)sidx[tid] * HW + h * WW + tid] = 1.0f;
            float term = sterm[tid];
#pragma unroll
            for (int off = 16; off > 0; off >>= 1)
                term += __shfl_xor_sync(0xffffffffu, term, off);
            if (tid == 0) {
                // COMMITMENT_COST / B = 0.25 / 4
                atomicAdd(out + kl_off, term * 0.0625f);
            }
        }
    }

    // ---- registration + self-reset for graph replay ----
    if (tid == 0) {
        int old = atomicAdd(&g_rowcnt[row], 256);
        if (old == NCHUNK + 7 * 256) {          // I'm the 8th consumer
            *(volatile int*)&g_rowcnt[row] = 0; // all siblings already passed
        }
    }
}

// ---------------------------------------------------------------------------
extern "C" void kernel_launch(void* const* d_in, const int* in_sizes, int n_in,
                              void* d_out, int out_size) {
    const float* x   = (const float*)d_in[0];
    const float* emb = (const float*)d_in[1];
    const float* gum = (const float*)d_in[2];
    float* out = (float*)d_out;

    // Output layout: [quantized (1048576)] [kl (1)] [one_hot (33554432)]
    const size_t oh_off = (size_t)out_size - OH_ELEMS;
    const size_t kl_off = oh_off - 1;

    kA<<<NRED + NZERO, 256>>>(x, gum, out, kl_off, oh_off);

    // kB with PDL: dispatches into slots freed during kA's tail; per-row
    // polling provides the fine-grained dependency, grid-sync only where the
    // full kA (one_hot zeroing) is required.
    {
        cudaLaunchConfig_t cfg = {};
        cfg.gridDim  = dim3(ROWS * 8, 1, 1);
        cfg.blockDim = dim3(256, 1, 1);
        cfg.dynamicSmemBytes = 0;
        cfg.stream = 0;
        cudaLaunchAttribute attr[1];
        attr[0].id = cudaLaunchAttributeProgrammaticStreamSerialization;
        attr[0].val.programmaticStreamSerializationAllowed = 1;
        cfg.attrs = attr;
        cfg.numAttrs = 1;
        cudaLaunchKernelEx(&cfg, kB, emb, out, kl_off, oh_off);
    }
}